// round 3
// baseline (speedup 1.0000x reference)
#include <cuda_runtime.h>
#include <math.h>

#define BB 64
#define TMAX 256
#define PP 64
#define DD 128
#define CC 10
#define TBASE 367

// Scratch (no cudaMalloc allowed)
__device__ int   d_len[BB];
__device__ int   d_off[BB + 1];
__device__ float d_E[TBASE * CC];                 // E[date*C + c]
__device__ float4 d_Y4[BB * CC * (PP / 4)];       // Y[b][c][p], viewed as float4 along p

// ---------------------------------------------------------------------------
// Kernel 1: per-row length (index of last nonzero date) + exclusive prefix sum
// 1 block x 1024 threads: 16 threads per row, each scans 16 strided elements.
// ---------------------------------------------------------------------------
__global__ void __launch_bounds__(1024) k_lengths(const int* __restrict__ dates) {
    __shared__ int s_len[BB];
    int tid = threadIdx.x;          // 0..1023
    int b   = tid >> 4;             // 0..63
    int k   = tid & 15;             // 0..15

    const int* row = dates + b * TMAX;
    int last = -1;
    #pragma unroll
    for (int i = 0; i < 16; ++i) {
        int t = k + i * 16;
        if (row[t] != 0) last = t;  // i increasing => last kept is max
    }
    // reduce max over the 16-thread sub-group (width=16 shfl)
    #pragma unroll
    for (int o = 8; o > 0; o >>= 1) {
        int other = __shfl_down_sync(0xffffffffu, last, o, 16);
        last = max(last, other);
    }
    if (k == 0) {
        int L = (last < 0) ? (TMAX - 1) : last;  // argmax-on-reversed semantics
        s_len[b] = L;
        d_len[b] = L;
    }
    __syncthreads();
    if (tid == 0) {
        int acc = 0;
        #pragma unroll
        for (int i = 0; i < BB; ++i) { d_off[i] = acc; acc += s_len[i]; }
        d_off[BB] = acc;
    }
}

// ---------------------------------------------------------------------------
// Kernel 2: E[date,c] = sinusoid_table[date,:] . W[c,:]
// One block per date (367 blocks, 128 threads). Table value computed in
// double to match the float64 numpy reference, then cast to fp32 for the dot.
// ---------------------------------------------------------------------------
__global__ void k_etab(const float* __restrict__ W) {
    int pos = blockIdx.x;        // 0..TBASE-1
    int j   = threadIdx.x;       // 0..127
    __shared__ float s_red[CC][4];

    double ang = (double)pos / pow((double)TBASE, (2.0 * (double)(j >> 1)) / (double)DD);
    float t = (j & 1) ? (float)cos(ang) : (float)sin(ang);

    #pragma unroll
    for (int c = 0; c < CC; ++c) {
        float v = t * W[c * DD + j];
        #pragma unroll
        for (int o = 16; o > 0; o >>= 1)
            v += __shfl_down_sync(0xffffffffu, v, o);
        if ((j & 31) == 0) s_red[c][j >> 5] = v;
    }
    __syncthreads();
    if (j < CC)
        d_E[pos * CC + j] = s_red[j][0] + s_red[j][1] + s_red[j][2] + s_red[j][3];
}

// ---------------------------------------------------------------------------
// Kernel 3: Y[b][c][p] = bias[c] + x[b,p,:] . W[c,:]
// One warp per (b,p). 8 warps / block -> 512 blocks.
// ---------------------------------------------------------------------------
__global__ void k_y(const float* __restrict__ x,
                    const float* __restrict__ W,
                    const float* __restrict__ bias) {
    int w    = blockIdx.x * 8 + (threadIdx.x >> 5);  // global warp id = b*P + p
    int lane = threadIdx.x & 31;
    int b = w / PP;
    int p = w % PP;

    const float4* x4 = (const float4*)x;
    float4 xv = x4[(size_t)(b * PP + p) * (DD / 4) + lane];

    const float4* W4 = (const float4*)W;
    float* Yf = (float*)d_Y4;

    #pragma unroll
    for (int c = 0; c < CC; ++c) {
        float4 wv = W4[c * (DD / 4) + lane];
        float v = xv.x * wv.x + xv.y * wv.y + xv.z * wv.z + xv.w * wv.w;
        #pragma unroll
        for (int o = 16; o > 0; o >>= 1)
            v += __shfl_down_sync(0xffffffffu, v, o);
        if (lane == 0)
            Yf[(b * CC + c) * PP + p] = v + bias[c];
    }
}

// ---------------------------------------------------------------------------
// Kernel 4: the write. grid = (TMAX, B), 160 threads/block.
// Each block handles one token (b,t): writes 160 float4 (= 640 floats) of
//   recons[n,c,p] = Y[b,c,p] + E[date,c]
// plus the 2 mask ints (as float values, appended after recons).
// ---------------------------------------------------------------------------
__global__ void __launch_bounds__(160) k_write(const int* __restrict__ dates,
                                               float* __restrict__ out) {
    int t = blockIdx.x;
    int b = blockIdx.y;
    int L = d_len[b];
    if (t >= L) return;

    int n    = d_off[b] + t;
    int date = dates[b * TMAX + t];

    int tid = threadIdx.x;      // 0..159
    int c   = tid >> 4;         // 0..9
    int p4  = tid & 15;         // 0..15

    float  e = d_E[date * CC + c];
    float4 y = d_Y4[(b * CC + c) * (PP / 4) + p4];
    float4 r = make_float4(y.x + e, y.y + e, y.z + e, y.w + e);

    ((float4*)out)[(size_t)n * 160 + tid] = r;

    // masks appended after recons: out[N*C*P + n*2 + {0,1}] = {b, t}
    if (tid < 2) {
        int Ntot = d_off[BB];
        size_t base = (size_t)Ntot * (CC * PP);
        out[base + (size_t)n * 2 + tid] = (tid == 0) ? (float)b : (float)t;
    }
}

// ---------------------------------------------------------------------------
extern "C" void kernel_launch(void* const* d_in, const int* in_sizes, int n_in,
                              void* d_out, int out_size) {
    const float* x     = (const float*)d_in[0];
    // d_in[1] = attentions (unused by the reference computation)
    const int*   dates = (const int*)d_in[2];
    const float* W     = (const float*)d_in[3];
    const float* bias  = (const float*)d_in[4];
    float* out = (float*)d_out;

    k_lengths<<<1, 1024>>>(dates);
    k_etab<<<TBASE, DD>>>(W);
    k_y<<<(BB * PP) / 8, 256>>>(x, W, bias);

    dim3 grid(TMAX, BB);
    k_write<<<grid, 160>>>(dates, out);
}

// round 4
// speedup vs baseline: 1.3977x; 1.3977x over previous
#include <cuda_runtime.h>
#include <math.h>

#define BB 64
#define TMAX 256
#define PP 64
#define DD 128
#define CC 10
#define TBASE 367

// Scratch (no cudaMalloc allowed)
__device__ int    d_len[BB];
__device__ int    d_off[BB + 1];
__device__ float  d_E[TBASE * CC];            // E[date*C + c]
__device__ float4 d_Y4[BB * CC * (PP / 4)];   // Y[b][c][p] as float4 along p

// k_setup role partition
#define NB_Y    512                 // blocks 0..511: Y (8 warps, one (b,p) per warp)
#define NB_E    184                 // blocks 512..695: E (2 dates per block)
#define BID_LEN (NB_Y + NB_E)       // block 696: lengths + prefix sum
#define NB_SETUP (BID_LEN + 1)

// ---------------------------------------------------------------------------
// Fused setup kernel: Y precompute + E table + ragged lengths/offsets.
// ---------------------------------------------------------------------------
__global__ void __launch_bounds__(256) k_setup(const float* __restrict__ x,
                                               const int*   __restrict__ dates,
                                               const float* __restrict__ W,
                                               const float* __restrict__ bias) {
    int bid = blockIdx.x;
    int tid = threadIdx.x;

    if (bid < NB_Y) {
        // ---- Y[b][c][p] = bias[c] + x[b,p,:] . W[c,:]  (one warp per (b,p))
        int w    = bid * 8 + (tid >> 5);
        int lane = tid & 31;
        int b = w / PP;
        int p = w % PP;

        const float4* x4 = (const float4*)x;
        float4 xv = x4[(size_t)(b * PP + p) * (DD / 4) + lane];
        const float4* W4 = (const float4*)W;
        float* Yf = (float*)d_Y4;

        #pragma unroll
        for (int c = 0; c < CC; ++c) {
            float4 wv = W4[c * (DD / 4) + lane];
            float v = fmaf(xv.x, wv.x, fmaf(xv.y, wv.y, fmaf(xv.z, wv.z, xv.w * wv.w)));
            #pragma unroll
            for (int o = 16; o > 0; o >>= 1)
                v += __shfl_down_sync(0xffffffffu, v, o);
            if (lane == 0)
                Yf[(b * CC + c) * PP + p] = v + bias[c];
        }
    } else if (bid < BID_LEN) {
        // ---- E[pos,c] = sinusoid_table[pos,:] . W[c,:]  (2 dates per block)
        __shared__ float s_red[2][CC][4];
        int sub = tid >> 7;          // 0/1: which date within the block
        int j   = tid & 127;         // 0..127: embedding dim
        int pos = (bid - NB_Y) * 2 + sub;

        float t = 0.0f;
        if (pos < TBASE) {
            double ang = (double)pos /
                         pow((double)TBASE, (2.0 * (double)(j >> 1)) / (double)DD);
            t = (j & 1) ? (float)cos(ang) : (float)sin(ang);
        }
        #pragma unroll
        for (int c = 0; c < CC; ++c) {
            float v = t * W[c * DD + j];
            #pragma unroll
            for (int o = 16; o > 0; o >>= 1)
                v += __shfl_down_sync(0xffffffffu, v, o);
            if ((j & 31) == 0) s_red[sub][c][j >> 5] = v;
        }
        __syncthreads();
        if (j < CC && pos < TBASE)
            d_E[pos * CC + j] =
                s_red[sub][j][0] + s_red[sub][j][1] + s_red[sub][j][2] + s_red[sub][j][3];
    } else {
        // ---- lengths: last-nonzero index per row, then exclusive prefix sum
        __shared__ int s_len[BB];
        int b = tid >> 2;            // 4 threads per row
        int k = tid & 3;
        const int4* row4 = (const int4*)(dates + b * TMAX);
        int last = -1;
        #pragma unroll
        for (int i = 0; i < 16; ++i) {
            int idx = k + i * 4;     // int4 index (i ascending => keep max)
            int4 v = row4[idx];
            int bt = idx * 4;
            if (v.x != 0) last = bt;
            if (v.y != 0) last = bt + 1;
            if (v.z != 0) last = bt + 2;
            if (v.w != 0) last = bt + 3;
        }
        last = max(last, __shfl_down_sync(0xffffffffu, last, 2, 4));
        last = max(last, __shfl_down_sync(0xffffffffu, last, 1, 4));
        if (k == 0) {
            int L = (last < 0) ? (TMAX - 1) : last;
            s_len[b] = L;
            d_len[b] = L;
        }
        __syncthreads();
        if (tid == 0) {
            int acc = 0;
            #pragma unroll
            for (int i = 0; i < BB; ++i) { d_off[i] = acc; acc += s_len[i]; }
            d_off[BB] = acc;
        }
    }
}

// ---------------------------------------------------------------------------
// Write kernel: grid (TMAX/TCHUNK, B), 320 threads (2 token slots x 160).
// Each block: one b, TCHUNK consecutive tokens. Y float4 cached in registers
// across the token loop; dates staged in shared; unroll x4 batches e-loads.
// ---------------------------------------------------------------------------
#define TCHUNK 32

__global__ void __launch_bounds__(320) k_write(const int* __restrict__ dates,
                                               float* __restrict__ out) {
    __shared__ int s_dates[TCHUNK];
    int b  = blockIdx.y;
    int t0 = blockIdx.x * TCHUNK;

    int L = d_len[b];
    if (t0 >= L) return;     // uniform per block

    int tid  = threadIdx.x;              // 0..319
    int slot = tid >= 160 ? 1 : 0;       // token parity slot (warps 0-4 / 5-9)
    int r    = tid - slot * 160;         // 0..159
    int c    = r >> 4;                   // 0..9
    int p4   = r & 15;                   // 0..15

    int n0   = d_off[b];
    int Ntot = d_off[BB];

    if (tid < TCHUNK) s_dates[tid] = dates[b * TMAX + t0 + tid];
    __syncthreads();

    float4 y = d_Y4[(b * CC + c) * (PP / 4) + p4];
    float4* out4 = (float4*)out;
    size_t mask_base = (size_t)Ntot * (CC * PP);

    #pragma unroll 4
    for (int i = 0; i < TCHUNK / 2; ++i) {
        int t = t0 + 2 * i + slot;
        if (t >= L) continue;
        int date = s_dates[2 * i + slot];
        float e = __ldg(&d_E[date * CC + c]);
        int n = n0 + t;
        out4[(size_t)n * 160 + r] = make_float4(y.x + e, y.y + e, y.z + e, y.w + e);
        if (r < 2)
            out[mask_base + (size_t)n * 2 + r] = (r == 0) ? (float)b : (float)t;
    }
}

// ---------------------------------------------------------------------------
extern "C" void kernel_launch(void* const* d_in, const int* in_sizes, int n_in,
                              void* d_out, int out_size) {
    const float* x     = (const float*)d_in[0];
    // d_in[1] = attentions (unused by the reference computation)
    const int*   dates = (const int*)d_in[2];
    const float* W     = (const float*)d_in[3];
    const float* bias  = (const float*)d_in[4];
    float* out = (float*)d_out;

    k_setup<<<NB_SETUP, 256>>>(x, dates, W, bias);

    dim3 grid(TMAX / TCHUNK, BB);
    k_write<<<grid, 320>>>(dates, out);
}